// round 1
// baseline (speedup 1.0000x reference)
#include <cuda_runtime.h>

// Problem constants (match reference)
#define BB   16
#define CC   32
#define HW   384
#define NKK  32
#define HID  128
#define KOUT (NKK * 9)   // 288

// Scratch (no allocations allowed in kernel_launch)
__device__ float g_pooled[BB * CC];        // [B, C] means
__device__ float g_kern[BB * NKK * 9];     // [B, NK, 3, 3] generated kernels

// ---------------------------------------------------------------------------
// Kernel 1: global average pool per (b, c) plane.
// One block per plane; float4 streaming reads; two-level reduction.
// ---------------------------------------------------------------------------
__global__ void pool_kernel(const float* __restrict__ x) {
    const int bc = blockIdx.x;                      // 0..B*C-1
    const float4* p = (const float4*)(x + (size_t)bc * HW * HW);
    const int n4 = HW * HW / 4;                     // 36864

    float sum = 0.f;
    for (int i = threadIdx.x; i < n4; i += blockDim.x) {
        float4 v = p[i];
        sum += (v.x + v.y) + (v.z + v.w);
    }

    __shared__ float red[32];
    #pragma unroll
    for (int o = 16; o; o >>= 1) sum += __shfl_xor_sync(0xffffffffu, sum, o);
    if ((threadIdx.x & 31) == 0) red[threadIdx.x >> 5] = sum;
    __syncthreads();
    if (threadIdx.x < 32) {
        float s = (threadIdx.x < (blockDim.x >> 5)) ? red[threadIdx.x] : 0.f;
        #pragma unroll
        for (int o = 16; o; o >>= 1) s += __shfl_xor_sync(0xffffffffu, s, o);
        if (threadIdx.x == 0) g_pooled[bc] = s * (1.f / (float)(HW * HW));
    }
}

// ---------------------------------------------------------------------------
// Kernel 2: tiny MLP  pooled[B,C] -> relu(pooled@w1+b1) -> @w2+b2 -> g_kern
// One block per batch sample, 288 threads.
// ---------------------------------------------------------------------------
__global__ void mlp_kernel(const float* __restrict__ w1, const float* __restrict__ b1,
                           const float* __restrict__ w2, const float* __restrict__ b2) {
    const int b = blockIdx.x;
    const int t = threadIdx.x;

    __shared__ float pooled_s[CC];
    __shared__ float hdn_s[HID];

    if (t < CC) pooled_s[t] = g_pooled[b * CC + t];
    __syncthreads();

    if (t < HID) {
        float acc = b1[t];
        #pragma unroll 8
        for (int i = 0; i < CC; i++) acc = fmaf(pooled_s[i], w1[i * HID + t], acc);
        hdn_s[t] = fmaxf(acc, 0.f);
    }
    __syncthreads();

    if (t < KOUT) {
        float acc = b2[t];
        #pragma unroll 8
        for (int i = 0; i < HID; i++) acc = fmaf(hdn_s[i], w2[i * KOUT + t], acc);
        g_kern[b * KOUT + t] = acc;
    }
}

// ---------------------------------------------------------------------------
// Kernel 3: per-sample depthwise 3x3 conv, pad=1.
// Block = (96,4) threads covering 8 output rows x 384 cols of one plane.
// Each thread: 2 output rows x 4 cols (two float4 stores), loading 4 input
// rows as (scalar left, float4 center, scalar right) with register reuse.
// ---------------------------------------------------------------------------
__global__ __launch_bounds__(384, 4)
void conv_kernel(const float* __restrict__ x, float* __restrict__ out) {
    const int plane = blockIdx.y;              // b*NK + nk
    const int b  = plane / NKK;
    const int ch = plane % NKK;                // channel index into x (C dims)

    const int tx   = threadIdx.x;              // 0..95
    const int ty   = threadIdx.y;              // 0..3
    const int row0 = blockIdx.x * 8 + ty * 2;  // first of 2 output rows
    const int col  = tx * 4;

    const float* __restrict__ ip = x   + ((size_t)b * CC + ch) * (size_t)(HW * HW);
    float*       __restrict__ op = out + (size_t)plane * (size_t)(HW * HW);

    float w[9];
    {
        const float* kp = g_kern + plane * 9;
        #pragma unroll
        for (int i = 0; i < 9; i++) w[i] = kp[i];
    }

    // Load 4 input rows: row0-1 .. row0+2
    float4 c[4];
    float  l[4], r[4];
    #pragma unroll
    for (int i = 0; i < 4; i++) {
        const int y = row0 - 1 + i;
        if (y >= 0 && y < HW) {
            const float* rp = ip + (size_t)y * HW;
            c[i] = *(const float4*)(rp + col);
            l[i] = (col > 0)       ? rp[col - 1] : 0.f;
            r[i] = (col + 4 < HW)  ? rp[col + 4] : 0.f;
        } else {
            c[i] = make_float4(0.f, 0.f, 0.f, 0.f);
            l[i] = 0.f; r[i] = 0.f;
        }
    }

    #pragma unroll
    for (int orow = 0; orow < 2; orow++) {
        float4 acc = make_float4(0.f, 0.f, 0.f, 0.f);
        #pragma unroll
        for (int dy = 0; dy < 3; dy++) {
            const int i = orow + dy;
            const float w0 = w[dy * 3 + 0];
            const float w1_ = w[dy * 3 + 1];
            const float w2_ = w[dy * 3 + 2];
            const float e0 = l[i];
            const float e1 = c[i].x, e2 = c[i].y, e3 = c[i].z, e4 = c[i].w;
            const float e5 = r[i];
            acc.x = fmaf(w0, e0, fmaf(w1_, e1, fmaf(w2_, e2, acc.x)));
            acc.y = fmaf(w0, e1, fmaf(w1_, e2, fmaf(w2_, e3, acc.y)));
            acc.z = fmaf(w0, e2, fmaf(w1_, e3, fmaf(w2_, e4, acc.z)));
            acc.w = fmaf(w0, e3, fmaf(w1_, e4, fmaf(w2_, e5, acc.w)));
        }
        *(float4*)(op + (size_t)(row0 + orow) * HW + col) = acc;
    }
}

// ---------------------------------------------------------------------------
extern "C" void kernel_launch(void* const* d_in, const int* in_sizes, int n_in,
                              void* d_out, int out_size) {
    const float* x  = (const float*)d_in[0];
    const float* w1 = (const float*)d_in[1];
    const float* b1 = (const float*)d_in[2];
    const float* w2 = (const float*)d_in[3];
    const float* b2 = (const float*)d_in[4];
    float* out = (float*)d_out;

    // 1) pooling: one block per (b,c) plane
    pool_kernel<<<BB * CC, 256>>>(x);

    // 2) kernel-generator MLP: one block per batch sample
    mlp_kernel<<<BB, KOUT>>>(w1, b1, w2, b2);

    // 3) depthwise dynamic conv
    dim3 grid(HW / 8, BB * NKK);   // 48 x 512
    dim3 block(96, 4);             // 384 threads
    conv_kernel<<<grid, block>>>(x, out);
}